// round 2
// baseline (speedup 1.0000x reference)
#include <cuda_runtime.h>

#define BATCH 16
#define NMAT  1024
#define DDIM  256
#define ITERS 101          // 100 scan steps + 1 final sinkhorn_step
#define NBLK_PER_B 9
#define GRID_SINK (BATCH * NBLK_PER_B)   // 144 blocks, all resident on 148 SMs
#define TPB_SINK  512                    // 16 warps

// ---------------- device scratch (no allocations allowed) ----------------
__device__ float g_nA[BATCH * NMAT * DDIM];                 // 16.8 MB
__device__ float g_nB[BATCH * NMAT * DDIM];                 // 16.8 MB
__device__ float g_K[(size_t)BATCH * NMAT * NMAT];          // 67.1 MB (L2-resident)
__device__ float g_part[2][BATCH][NBLK_PER_B][NMAT];        // double-buffered col partials
__device__ unsigned g_bar_count;
__device__ unsigned g_bar_gen;

// ---------------- l2 normalize: warp per row (256 elems) ----------------
__global__ void norm_kernel(const float* __restrict__ in, int which) {
    int w = threadIdx.x >> 5, lane = threadIdx.x & 31;
    int row = blockIdx.x * 8 + w;                      // 2048 blocks * 8 = 16384 rows
    const float4* src = reinterpret_cast<const float4*>(in) + (size_t)row * 64;
    float4 x0 = src[lane];
    float4 x1 = src[lane + 32];
    float s = x0.x * x0.x + x0.y * x0.y + x0.z * x0.z + x0.w * x0.w
            + x1.x * x1.x + x1.y * x1.y + x1.z * x1.z + x1.w * x1.w;
    #pragma unroll
    for (int off = 16; off; off >>= 1) s += __shfl_xor_sync(0xffffffffu, s, off);
    float r = rsqrtf(fmaxf(s, 1e-12f));
    float* dst = (which ? g_nB : g_nA) + (size_t)row * 256;
    float4 y0 = make_float4(x0.x * r, x0.y * r, x0.z * r, x0.w * r);
    float4 y1 = make_float4(x1.x * r, x1.y * r, x1.z * r, x1.w * r);
    reinterpret_cast<float4*>(dst)[lane]      = y0;
    reinterpret_cast<float4*>(dst)[lane + 32] = y1;
}

// ---------------- GEMM: S = nA * nB^T per batch, K = exp(5*clamp(S)) ----------------
// grid (8, 8, 16), block 256, 128x128 tile, 8x8 per thread, BK=32
__global__ void __launch_bounds__(256) gemm_expk_kernel(float* __restrict__ Sout) {
    __shared__ float As[32 * 128];   // [k][i]
    __shared__ float Bs[32 * 128];   // [k][j]
    const int b  = blockIdx.z;
    const int i0 = blockIdx.y * 128;
    const int j0 = blockIdx.x * 128;
    const float* Ag = g_nA + (size_t)b * NMAT * DDIM;
    const float* Bg = g_nB + (size_t)b * NMAT * DDIM;
    const int tid = threadIdx.x;
    const int tx = tid & 15, ty = tid >> 4;
    const int lr = tid >> 3;     // 0..31 row within chunk
    const int lc = tid & 7;      // float4 group within 32 k-cols

    float acc[8][8];
    #pragma unroll
    for (int i = 0; i < 8; i++)
        #pragma unroll
        for (int j = 0; j < 8; j++) acc[i][j] = 0.f;

    for (int kc = 0; kc < 8; kc++) {
        __syncthreads();
        #pragma unroll
        for (int g = 0; g < 4; g++) {
            int row = lr + 32 * g;
            float4 av = *reinterpret_cast<const float4*>(
                &Ag[(size_t)(i0 + row) * DDIM + kc * 32 + lc * 4]);
            As[(lc * 4 + 0) * 128 + row] = av.x;
            As[(lc * 4 + 1) * 128 + row] = av.y;
            As[(lc * 4 + 2) * 128 + row] = av.z;
            As[(lc * 4 + 3) * 128 + row] = av.w;
            float4 bv = *reinterpret_cast<const float4*>(
                &Bg[(size_t)(j0 + row) * DDIM + kc * 32 + lc * 4]);
            Bs[(lc * 4 + 0) * 128 + row] = bv.x;
            Bs[(lc * 4 + 1) * 128 + row] = bv.y;
            Bs[(lc * 4 + 2) * 128 + row] = bv.z;
            Bs[(lc * 4 + 3) * 128 + row] = bv.w;
        }
        __syncthreads();
        #pragma unroll
        for (int k = 0; k < 32; k++) {
            float4 a0 = *reinterpret_cast<const float4*>(&As[k * 128 + ty * 8]);
            float4 a1 = *reinterpret_cast<const float4*>(&As[k * 128 + ty * 8 + 4]);
            float4 b0 = *reinterpret_cast<const float4*>(&Bs[k * 128 + tx * 8]);
            float4 b1 = *reinterpret_cast<const float4*>(&Bs[k * 128 + tx * 8 + 4]);
            float a[8] = {a0.x, a0.y, a0.z, a0.w, a1.x, a1.y, a1.z, a1.w};
            float bb[8] = {b0.x, b0.y, b0.z, b0.w, b1.x, b1.y, b1.z, b1.w};
            #pragma unroll
            for (int ii = 0; ii < 8; ii++)
                #pragma unroll
                for (int jj = 0; jj < 8; jj++)
                    acc[ii][jj] = fmaf(a[ii], bb[jj], acc[ii][jj]);
        }
    }

    #pragma unroll
    for (int ii = 0; ii < 8; ii++) {
        int i = i0 + ty * 8 + ii;
        size_t base = ((size_t)b << 20) + (size_t)i * NMAT + j0 + tx * 8;
        float4 s0 = make_float4(acc[ii][0], acc[ii][1], acc[ii][2], acc[ii][3]);
        float4 s1 = make_float4(acc[ii][4], acc[ii][5], acc[ii][6], acc[ii][7]);
        *reinterpret_cast<float4*>(&Sout[base])     = s0;
        *reinterpret_cast<float4*>(&Sout[base + 4]) = s1;
        float4 k0, k1;
        k0.x = __expf(5.f * fminf(fmaxf(s0.x, -3.f), 3.f));
        k0.y = __expf(5.f * fminf(fmaxf(s0.y, -3.f), 3.f));
        k0.z = __expf(5.f * fminf(fmaxf(s0.z, -3.f), 3.f));
        k0.w = __expf(5.f * fminf(fmaxf(s0.w, -3.f), 3.f));
        k1.x = __expf(5.f * fminf(fmaxf(s1.x, -3.f), 3.f));
        k1.y = __expf(5.f * fminf(fmaxf(s1.y, -3.f), 3.f));
        k1.z = __expf(5.f * fminf(fmaxf(s1.z, -3.f), 3.f));
        k1.w = __expf(5.f * fminf(fmaxf(s1.w, -3.f), 3.f));
        *reinterpret_cast<float4*>(&g_K[base])     = k0;
        *reinterpret_cast<float4*>(&g_K[base + 4]) = k1;
    }
}

// ---------------- grid barrier (all 144 blocks resident by construction) ----------------
__device__ __forceinline__ void grid_barrier() {
    __syncthreads();
    if (threadIdx.x == 0) {
        __threadfence();
        unsigned gen = *reinterpret_cast<volatile unsigned*>(&g_bar_gen);
        if (atomicAdd(&g_bar_count, 1u) == GRID_SINK - 1) {
            g_bar_count = 0;
            __threadfence();
            atomicAdd(&g_bar_gen, 1u);
        } else {
            while (*reinterpret_cast<volatile unsigned*>(&g_bar_gen) == gen) {
                __nanosleep(64);
            }
        }
        __threadfence();
    }
    __syncthreads();
}

// ---------------- persistent Sinkhorn: 101 fused (row+col) passes over K ----------------
// Block = (batch b, slice r of 9). Warp processes whole rows; lane owns cols {4*lane + 128k + c}.
__global__ void __launch_bounds__(TPB_SINK, 1) sinkhorn_kernel(float* __restrict__ Pout) {
    const int b = blockIdx.x / NBLK_PER_B;
    const int r = blockIdx.x % NBLK_PER_B;
    const int row0  = r * 114;
    const int nrows = (r == 8) ? 112 : 114;          // 8*114 + 112 = 1024
    const int tid = threadIdx.x, w = tid >> 5, lane = tid & 31;

    extern __shared__ float sm[];
    float* v_s     = sm;            // 1024
    float* u_s     = sm + 1024;     // 128 (114 used)
    float* colpart = sm + 1152;     // 16 * 1024

    const float* Kb = g_K + ((size_t)b << 20);

    float vreg[32];
    float colacc[32];

    for (int t = 0; t < ITERS; t++) {
        const int wb = t & 1;        // buffer written this iteration
        // ---- phase A: build v ----
        if (t == 0) {
            #pragma unroll
            for (int m = 0; m < 32; m++) vreg[m] = 1.0f;
        } else {
            const int rb = wb ^ 1;   // buffer written by iteration t-1
            for (int c = tid; c < NMAT; c += TPB_SINK) {
                float s = 0.f;
                #pragma unroll
                for (int rr = 0; rr < NBLK_PER_B; rr++) s += g_part[rb][b][rr][c];
                v_s[c] = 1.0f / s;
            }
            __syncthreads();
            #pragma unroll
            for (int k = 0; k < 8; k++) {
                float4 vv = *reinterpret_cast<const float4*>(&v_s[128 * k + 4 * lane]);
                vreg[4 * k + 0] = vv.x; vreg[4 * k + 1] = vv.y;
                vreg[4 * k + 2] = vv.z; vreg[4 * k + 3] = vv.w;
            }
        }
        #pragma unroll
        for (int m = 0; m < 32; m++) colacc[m] = 0.f;

        // ---- phase B: fused row matvec + col accumulate (one K pass) ----
        for (int il = w; il < nrows; il += 16) {
            const int i = row0 + il;
            const float4* Krow = reinterpret_cast<const float4*>(Kb + (size_t)i * NMAT);
            float4 kk[8];
            float dot = 0.f;
            #pragma unroll
            for (int k = 0; k < 8; k++) {
                kk[k] = Krow[32 * k + lane];
                dot = fmaf(kk[k].x, vreg[4 * k + 0], dot);
                dot = fmaf(kk[k].y, vreg[4 * k + 1], dot);
                dot = fmaf(kk[k].z, vreg[4 * k + 2], dot);
                dot = fmaf(kk[k].w, vreg[4 * k + 3], dot);
            }
            #pragma unroll
            for (int off = 16; off; off >>= 1) dot += __shfl_xor_sync(0xffffffffu, dot, off);
            float u = 1.0f / dot;
            if (lane == 0) u_s[il] = u;
            #pragma unroll
            for (int k = 0; k < 8; k++) {
                colacc[4 * k + 0] = fmaf(u, kk[k].x, colacc[4 * k + 0]);
                colacc[4 * k + 1] = fmaf(u, kk[k].y, colacc[4 * k + 1]);
                colacc[4 * k + 2] = fmaf(u, kk[k].z, colacc[4 * k + 2]);
                colacc[4 * k + 3] = fmaf(u, kk[k].w, colacc[4 * k + 3]);
            }
        }

        // ---- phase C: per-warp partials -> block partial -> global ----
        #pragma unroll
        for (int k = 0; k < 8; k++) {
            *reinterpret_cast<float4*>(&colpart[w * 1024 + 128 * k + 4 * lane]) =
                make_float4(colacc[4 * k + 0], colacc[4 * k + 1],
                            colacc[4 * k + 2], colacc[4 * k + 3]);
        }
        __syncthreads();
        for (int c = tid; c < NMAT; c += TPB_SINK) {
            float s = 0.f;
            #pragma unroll
            for (int ww = 0; ww < 16; ww++) s += colpart[ww * 1024 + c];
            g_part[wb][b][r][c] = s;
        }
        grid_barrier();   // includes the leading __syncthreads()
    }

    // ---- final: v from last partials (buffer (ITERS-1)&1 == 0), P_out = u*K*v ----
    {
        const int fb = (ITERS - 1) & 1;
        for (int c = tid; c < NMAT; c += TPB_SINK) {
            float s = 0.f;
            #pragma unroll
            for (int rr = 0; rr < NBLK_PER_B; rr++) s += g_part[fb][b][rr][c];
            v_s[c] = 1.0f / s;
        }
        __syncthreads();
        #pragma unroll
        for (int k = 0; k < 8; k++) {
            float4 vv = *reinterpret_cast<const float4*>(&v_s[128 * k + 4 * lane]);
            vreg[4 * k + 0] = vv.x; vreg[4 * k + 1] = vv.y;
            vreg[4 * k + 2] = vv.z; vreg[4 * k + 3] = vv.w;
        }
        for (int il = w; il < nrows; il += 16) {
            const int i = row0 + il;
            const float4* Krow = reinterpret_cast<const float4*>(Kb + (size_t)i * NMAT);
            float u = u_s[il];
            float4* Orow = reinterpret_cast<float4*>(Pout + ((size_t)b << 20) + (size_t)i * NMAT);
            #pragma unroll
            for (int k = 0; k < 8; k++) {
                float4 kk = Krow[32 * k + lane];
                float4 o;
                o.x = u * kk.x * vreg[4 * k + 0];
                o.y = u * kk.y * vreg[4 * k + 1];
                o.z = u * kk.z * vreg[4 * k + 2];
                o.w = u * kk.w * vreg[4 * k + 3];
                Orow[32 * k + lane] = o;
            }
        }
    }
}

// ---------------- launch ----------------
extern "C" void kernel_launch(void* const* d_in, const int* in_sizes, int n_in,
                              void* d_out, int out_size) {
    const float* fA = (const float*)d_in[0];
    const float* fB = (const float*)d_in[1];
    float* out  = (float*)d_out;
    float* Pout = out;                                        // P_out: [16,1024,1024]
    float* Sout = out + (size_t)BATCH * NMAT * NMAT;          // Sij:   [16,1024,1024]

    norm_kernel<<<2048, 256>>>(fA, 0);
    norm_kernel<<<2048, 256>>>(fB, 1);

    dim3 ggrid(8, 8, BATCH);
    gemm_expk_kernel<<<ggrid, 256>>>(Sout);

    const int smem_bytes = (1024 + 128 + 16 * 1024) * sizeof(float);   // 70144
    cudaFuncSetAttribute(sinkhorn_kernel,
                         cudaFuncAttributeMaxDynamicSharedMemorySize, smem_bytes);
    sinkhorn_kernel<<<GRID_SINK, TPB_SINK, smem_bytes>>>(Pout);
}